// round 3
// baseline (speedup 1.0000x reference)
#include <cuda_runtime.h>
#include <cstdint>

// Problem shape (fixed by dataset: B=2048, S=2048, H=64)
#define BB 2048
#define SS 2048
#define HH 64
#define EPSV 1e-6f
#define FULLMASK 0xFFFFFFFFu

typedef unsigned long long ull;

__device__ __forceinline__ ull fma2(ull a, ull b, ull c) {
    ull d;
    asm("fma.rn.f32x2 %0, %1, %2, %3;" : "=l"(d) : "l"(a), "l"(b), "l"(c));
    return d;
}
__device__ __forceinline__ ull add2(ull a, ull b) {
    ull d;
    asm("add.rn.f32x2 %0, %1, %2;" : "=l"(d) : "l"(a), "l"(b));
    return d;
}
__device__ __forceinline__ float2 unpack2(ull a) {
    float2 r;
    asm("mov.b64 {%0, %1}, %2;" : "=f"(r.x), "=f"(r.y) : "l"(a));
    return r;
}
// softplus(x) = max(x,0) + log1p(exp(-|x|)), fast MUFU path with log1p correction
__device__ __forceinline__ float softplus_fast(float x) {
    float t = __expf(-fabsf(x));
    float u = 1.f + t;
    float lg = __logf(u) + __fdividef(t - (u - 1.f), u);
    return fmaxf(x, 0.f) + lg;
}

// sigma0 scratch
__device__ float g_sig0[BB];

// --------------------------------------------------------------------------
// Kernel 1: unbiased variance per row -> g_sig0[b] and out[b*S + 0]
// --------------------------------------------------------------------------
__global__ void __launch_bounds__(256) var_kernel(const float* __restrict__ res,
                                                  float* __restrict__ out) {
    int b = blockIdx.x;
    const float* row = res + (size_t)b * SS;
    float s = 0.f, s2 = 0.f;
    for (int i = threadIdx.x; i < SS; i += 256) {
        float v = row[i];
        s += v;
        s2 = fmaf(v, v, s2);
    }
#pragma unroll
    for (int o = 16; o; o >>= 1) {
        s  += __shfl_xor_sync(FULLMASK, s,  o);
        s2 += __shfl_xor_sync(FULLMASK, s2, o);
    }
    __shared__ float sh[16];
    int w = threadIdx.x >> 5, l = threadIdx.x & 31;
    if (l == 0) { sh[w] = s; sh[w + 8] = s2; }
    __syncthreads();
    if (threadIdx.x == 0) {
        float S1 = 0.f, S2 = 0.f;
#pragma unroll
        for (int i = 0; i < 8; i++) { S1 += sh[i]; S2 += sh[i + 8]; }
        float var = (S2 - S1 * S1 / (float)SS) / (float)(SS - 1);
        g_sig0[b] = var;
        out[(size_t)b * SS] = var;
    }
}

// --------------------------------------------------------------------------
// Kernel 2: recurrence. One warp = 2 batch rows. W_hh rows in registers
// (f32x2-packed along k), h ping-pong in per-warp shared (LDS.128 broadcast).
// sigma path refactored: fc.h_t = u.h_{t-1} + p1*eps^2 + p2*sigma + c with
// u = fc^T W_hh precomputed -> sigma dot runs on REGISTER h in parallel with
// the shared-mem matvec; butterfly shfl tree replaces R1's (unsupported) redux.
// --------------------------------------------------------------------------
__global__ void __launch_bounds__(128) rnn_kernel(
    const float* __restrict__ res,   // [B][S]
    const float* __restrict__ Wih,   // [64][2]
    const float* __restrict__ bih,   // [64]
    const float* __restrict__ Whh,   // [64][64]
    const float* __restrict__ bhh,   // [64]
    const float* __restrict__ fcw,   // [64]
    const float* __restrict__ fcb1,  // [1]
    float* __restrict__ out)         // [B][S]
{
    const int lane = threadIdx.x & 31;
    const int wip  = threadIdx.x >> 5;
    const int wg   = blockIdx.x * 4 + wip;
    const int b0   = 2 * wg, b1 = 2 * wg + 1;
    const int r0   = lane, r1 = lane + 32;

    // W_hh rows for this lane, packed f32x2 along k
    ull w0[32], w1[32];
    {
        const ull* p0v = (const ull*)(Whh + r0 * HH);
        const ull* p1v = (const ull*)(Whh + r1 * HH);
#pragma unroll
        for (int i = 0; i < 32; i++) { w0[i] = p0v[i]; w1[i] = p1v[i]; }
    }
    const float wih00 = Wih[r0 * 2], wih01 = Wih[r0 * 2 + 1];
    const float wih10 = Wih[r1 * 2], wih11 = Wih[r1 * 2 + 1];
    const float bb0 = bih[r0] + bhh[r0];
    const float bb1 = bih[r1] + bhh[r1];

    // Precompute u[r0], u[r1] = column dots fc^T W_hh (coalesced across lanes),
    // and lane-redundant scalars p1, p2, c.
    float u0 = 0.f, u1 = 0.f, p1s = 0.f, p2s = 0.f, c = fcb1[0];
#pragma unroll 4
    for (int j = 0; j < HH; j++) {
        float f = fcw[j];
        u0  = fmaf(f, Whh[j * HH + r0], u0);
        u1  = fmaf(f, Whh[j * HH + r1], u1);
        p1s = fmaf(f, Wih[2 * j],     p1s);
        p2s = fmaf(f, Wih[2 * j + 1], p2s);
        c   = fmaf(f, bih[j] + bhh[j], c);
    }

    // [warp][pingpong][batch-of-2][64]
    __shared__ __align__(16) float hbuf[4][2][2][HH];

    hbuf[wip][0][0][r0] = 0.f; hbuf[wip][0][0][r1] = 0.f;
    hbuf[wip][0][1][r0] = 0.f; hbuf[wip][0][1][r1] = 0.f;
    __syncwarp();

    float sigA = g_sig0[b0];
    float sigB = g_sig0[b1];
    const float* resA = res + (size_t)b0 * SS;
    const float* resB = res + (size_t)b1 * SS;
    float* outA = out + (size_t)b0 * SS;
    float* outB = out + (size_t)b1 * SS;

    float eA = resA[0], eB = resB[0];
    // register-resident h of previous step (this lane's rows)
    float h0a = 0.f, h1a = 0.f, h0b = 0.f, h1b = 0.f;
    int p = 0;

#pragma unroll 1
    for (int t = 1; t < SS; ++t) {
        const float e2a = eA * eA, e2b = eB * eB;
        eA = resA[t]; eB = resB[t];

        // ---- sigma dot from previous h (registers) — issued first so the
        // butterfly latency overlaps the matvec issue stream ----
        float dA = fmaf(u0, h0a, u1 * h1a);
        float dB = fmaf(u0, h0b, u1 * h1b);
#pragma unroll
        for (int o = 16; o; o >>= 1) {
            dA += __shfl_xor_sync(FULLMASK, dA, o);
            dB += __shfl_xor_sync(FULLMASK, dB, o);
        }

        // ---- matvec from shared h_{t-1}: 8 independent f32x2 chains ----
        const float* hA = hbuf[wip][p][0];
        const float* hB = hbuf[wip][p][1];
        ull x0a = 0ull, y0a = 0ull, x1a = 0ull, y1a = 0ull;
        ull x0b = 0ull, y0b = 0ull, x1b = 0ull, y1b = 0ull;
#pragma unroll
        for (int i = 0; i < 16; i++) {
            ulonglong2 ha = *(const ulonglong2*)(hA + 4 * i);
            ulonglong2 hb = *(const ulonglong2*)(hB + 4 * i);
            x0a = fma2(w0[2 * i],     ha.x, x0a);
            y0a = fma2(w0[2 * i + 1], ha.y, y0a);
            x1a = fma2(w1[2 * i],     ha.x, x1a);
            y1a = fma2(w1[2 * i + 1], ha.y, y1a);
            x0b = fma2(w0[2 * i],     hb.x, x0b);
            y0b = fma2(w0[2 * i + 1], hb.y, y0b);
            x1b = fma2(w1[2 * i],     hb.x, x1b);
            y1b = fma2(w1[2 * i + 1], hb.y, y1b);
        }

        // ---- sigma (needs dA/dB; overlaps matvec issue) ----
        float xA = dA + fmaf(p1s, e2a, fmaf(p2s, sigA, c));
        float xB = dB + fmaf(p1s, e2b, fmaf(p2s, sigB, c));
        float nsA = softplus_fast(xA) + EPSV;
        float nsB = softplus_fast(xB) + EPSV;

        // ---- combine h (uses OLD sigma) ----
        float2 v;
        v = unpack2(add2(x0a, y0a));
        h0a = (v.x + v.y) + fmaf(e2a, wih00, fmaf(sigA, wih01, bb0));
        v = unpack2(add2(x1a, y1a));
        h1a = (v.x + v.y) + fmaf(e2a, wih10, fmaf(sigA, wih11, bb1));
        v = unpack2(add2(x0b, y0b));
        h0b = (v.x + v.y) + fmaf(e2b, wih00, fmaf(sigB, wih01, bb0));
        v = unpack2(add2(x1b, y1b));
        h1b = (v.x + v.y) + fmaf(e2b, wih10, fmaf(sigB, wih11, bb1));

        // ---- publish new h, advance ----
        float* nA = hbuf[wip][p ^ 1][0];
        float* nB = hbuf[wip][p ^ 1][1];
        nA[r0] = h0a; nA[r1] = h1a;
        nB[r0] = h0b; nB[r1] = h1b;
        __syncwarp();

        sigA = nsA; sigB = nsB;
        if (lane == 0)      outA[t] = nsA;
        else if (lane == 1) outB[t] = nsB;

        p ^= 1;
    }
}

// --------------------------------------------------------------------------
extern "C" void kernel_launch(void* const* d_in, const int* in_sizes, int n_in,
                              void* d_out, int out_size) {
    const float* res  = (const float*)d_in[0];
    const float* Wih  = (const float*)d_in[1];
    const float* bih  = (const float*)d_in[2];
    const float* Whh  = (const float*)d_in[3];
    const float* bhh  = (const float*)d_in[4];
    const float* fcw  = (const float*)d_in[5];
    const float* fcb  = (const float*)d_in[6];
    float* out = (float*)d_out;

    var_kernel<<<BB, 256>>>(res, out);
    rnn_kernel<<<BB / 8, 128>>>(res, Wih, bih, Whh, bhh, fcw, fcb, out);
}

// round 4
// speedup vs baseline: 1.3522x; 1.3522x over previous
#include <cuda_runtime.h>
#include <cstdint>

// Problem shape (fixed by dataset: B=2048, S=2048, H=64)
#define BB 2048
#define SS 2048
#define HH 64
#define EPSV 1e-6f
#define FULLMASK 0xFFFFFFFFu

typedef unsigned long long ull;

__device__ __forceinline__ ull fma2(ull a, ull b, ull c) {
    ull d;
    asm("fma.rn.f32x2 %0, %1, %2, %3;" : "=l"(d) : "l"(a), "l"(b), "l"(c));
    return d;
}
__device__ __forceinline__ ull add2(ull a, ull b) {
    ull d;
    asm("add.rn.f32x2 %0, %1, %2;" : "=l"(d) : "l"(a), "l"(b));
    return d;
}
__device__ __forceinline__ float2 unpack2(ull a) {
    float2 r;
    asm("mov.b64 {%0, %1}, %2;" : "=f"(r.x), "=f"(r.y) : "l"(a));
    return r;
}
// softplus(x) = max(x,0) + log1p(exp(-|x|)), fast MUFU path with log1p correction
__device__ __forceinline__ float softplus_fast(float x) {
    float t = __expf(-fabsf(x));
    float u = 1.f + t;
    float lg = __logf(u) + __fdividef(t - (u - 1.f), u);
    return fmaxf(x, 0.f) + lg;
}

// sigma0 scratch
__device__ float g_sig0[BB];

// --------------------------------------------------------------------------
// Kernel 1: unbiased variance per row -> g_sig0[b] and out[b*S + 0]
// --------------------------------------------------------------------------
__global__ void __launch_bounds__(256) var_kernel(const float* __restrict__ res,
                                                  float* __restrict__ out) {
    int b = blockIdx.x;
    const float* row = res + (size_t)b * SS;
    float s = 0.f, s2 = 0.f;
    for (int i = threadIdx.x; i < SS; i += 256) {
        float v = row[i];
        s += v;
        s2 = fmaf(v, v, s2);
    }
#pragma unroll
    for (int o = 16; o; o >>= 1) {
        s  += __shfl_xor_sync(FULLMASK, s,  o);
        s2 += __shfl_xor_sync(FULLMASK, s2, o);
    }
    __shared__ float sh[16];
    int w = threadIdx.x >> 5, l = threadIdx.x & 31;
    if (l == 0) { sh[w] = s; sh[w + 8] = s2; }
    __syncthreads();
    if (threadIdx.x == 0) {
        float S1 = 0.f, S2 = 0.f;
#pragma unroll
        for (int i = 0; i < 8; i++) { S1 += sh[i]; S2 += sh[i + 8]; }
        float var = (S2 - S1 * S1 / (float)SS) / (float)(SS - 1);
        g_sig0[b] = var;
        out[(size_t)b * SS] = var;
    }
}

// --------------------------------------------------------------------------
// Kernel 2: recurrence. ONE warp = ONE batch row (2048 warps total).
// Lane owns output rows lane and lane+32; W_hh rows in registers
// (f32x2-packed along k); h ping-pong in per-warp shared (LDS.128 broadcast).
// sigma path: fc.h_t = u.h_{t-1} + p1*eps^2 + p2*sigma + c (u = fc^T W_hh
// precomputed), so the sigma dot runs on REGISTER h in parallel with the
// matvec and its shuffle/softplus latency is hidden by co-resident warps.
// --------------------------------------------------------------------------
__global__ void __launch_bounds__(128, 3) rnn_kernel(
    const float* __restrict__ res,   // [B][S]
    const float* __restrict__ Wih,   // [64][2]
    const float* __restrict__ bih,   // [64]
    const float* __restrict__ Whh,   // [64][64]
    const float* __restrict__ bhh,   // [64]
    const float* __restrict__ fcw,   // [64]
    const float* __restrict__ fcb1,  // [1]
    float* __restrict__ out)         // [B][S]
{
    const int lane = threadIdx.x & 31;
    const int wip  = threadIdx.x >> 5;
    const int b    = blockIdx.x * 4 + wip;      // batch row (0..2047)
    const int r0   = lane, r1 = lane + 32;

    // W_hh rows for this lane, packed f32x2 along k
    ull w0[32], w1[32];
    {
        const ull* p0v = (const ull*)(Whh + r0 * HH);
        const ull* p1v = (const ull*)(Whh + r1 * HH);
#pragma unroll
        for (int i = 0; i < 32; i++) { w0[i] = p0v[i]; w1[i] = p1v[i]; }
    }
    const float wih00 = Wih[r0 * 2], wih01 = Wih[r0 * 2 + 1];
    const float wih10 = Wih[r1 * 2], wih11 = Wih[r1 * 2 + 1];
    const float bb0 = bih[r0] + bhh[r0];
    const float bb1 = bih[r1] + bhh[r1];

    // u = fc^T W_hh (per-lane columns r0, r1) and lane-redundant p1, p2, c
    float u0 = 0.f, u1 = 0.f, p1s = 0.f, p2s = 0.f, c = fcb1[0];
#pragma unroll 4
    for (int j = 0; j < HH; j++) {
        float f = fcw[j];
        u0  = fmaf(f, Whh[j * HH + r0], u0);
        u1  = fmaf(f, Whh[j * HH + r1], u1);
        p1s = fmaf(f, Wih[2 * j],     p1s);
        p2s = fmaf(f, Wih[2 * j + 1], p2s);
        c   = fmaf(f, bih[j] + bhh[j], c);
    }

    // [warp][pingpong][64] ; 2 KB static
    __shared__ __align__(16) float hbuf[4][2][HH];

    hbuf[wip][0][r0] = 0.f;
    hbuf[wip][0][r1] = 0.f;
    __syncwarp();

    float sig = g_sig0[b];
    const float* resB = res + (size_t)b * SS;
    float* outB = out + (size_t)b * SS;

    float e = resB[0];
    float h0 = 0.f, h1 = 0.f;   // this lane's rows of h_{t-1} (registers)
    int p = 0;

#pragma unroll 1
    for (int t = 1; t < SS; ++t) {
        const float e2 = e * e;
        e = resB[t];  // prefetch next eps (last iter value unused)

        // ---- sigma dot from previous h (registers); butterfly latency is
        // off the h->h critical path and hidden by co-resident warps ----
        float d = fmaf(u0, h0, u1 * h1);
#pragma unroll
        for (int o = 16; o; o >>= 1) d += __shfl_xor_sync(FULLMASK, d, o);

        // ---- matvec from shared h_{t-1}: 4 independent f32x2 chains ----
        const float* h = hbuf[wip][p];
        ull x0 = 0ull, y0 = 0ull, x1 = 0ull, y1 = 0ull;
#pragma unroll
        for (int i = 0; i < 16; i++) {
            ulonglong2 hv = *(const ulonglong2*)(h + 4 * i);  // LDS.128 bcast
            x0 = fma2(w0[2 * i],     hv.x, x0);
            y0 = fma2(w0[2 * i + 1], hv.y, y0);
            x1 = fma2(w1[2 * i],     hv.x, x1);
            y1 = fma2(w1[2 * i + 1], hv.y, y1);
        }

        // ---- sigma (overlaps matvec issue) ----
        float xs = d + fmaf(p1s, e2, fmaf(p2s, sig, c));
        float ns = softplus_fast(xs) + EPSV;

        // ---- combine h (uses OLD sigma) ----
        float2 v;
        v = unpack2(add2(x0, y0));
        h0 = (v.x + v.y) + fmaf(e2, wih00, fmaf(sig, wih01, bb0));
        v = unpack2(add2(x1, y1));
        h1 = (v.x + v.y) + fmaf(e2, wih10, fmaf(sig, wih11, bb1));

        // ---- publish new h ----
        float* nb = hbuf[wip][p ^ 1];
        nb[r0] = h0;
        nb[r1] = h1;
        __syncwarp();

        sig = ns;
        if (lane == 0) outB[t] = ns;
        p ^= 1;
    }
}

// --------------------------------------------------------------------------
extern "C" void kernel_launch(void* const* d_in, const int* in_sizes, int n_in,
                              void* d_out, int out_size) {
    const float* res  = (const float*)d_in[0];
    const float* Wih  = (const float*)d_in[1];
    const float* bih  = (const float*)d_in[2];
    const float* Whh  = (const float*)d_in[3];
    const float* bhh  = (const float*)d_in[4];
    const float* fcw  = (const float*)d_in[5];
    const float* fcb  = (const float*)d_in[6];
    float* out = (float*)d_out;

    var_kernel<<<BB, 256>>>(res, out);
    rnn_kernel<<<BB / 4, 128>>>(res, Wih, bih, Whh, bhh, fcw, fcb, out);
}